// round 7
// baseline (speedup 1.0000x reference)
#include <cuda_runtime.h>
#include <cuda_bf16.h>
#include <cstdint>

#define NN 100000
#define EE 1600000

// ---------------- device scratch (static, no allocation) ----------------
__device__ float g_h  [(size_t)NN * 128];   // combine output  (GEMM input)
__device__ float g_hid[(size_t)NN * 128];   // after first linear + relu
__device__ float g_x  [(size_t)NN * 128];   // layer output features

__device__ int g_deg[NN];
__device__ int g_scan[NN];
__device__ int g_bsums[512];
__device__ int g_ptr[NN + 1];
__device__ int g_cursor[NN];
__device__ int g_csr[EE];

// ---------------- CSR build ----------------
__global__ void k_zero_deg() {
    int i = blockIdx.x * blockDim.x + threadIdx.x;
    if (i < NN) g_deg[i] = 0;
}

__global__ void k_count(const int* __restrict__ ei) {
    int e = blockIdx.x * blockDim.x + threadIdx.x;
    if (e < EE) atomicAdd(&g_deg[ei[EE + e]], 1);
}

__global__ void k_scan1() {   // 256 threads/block, grid covers NN
    __shared__ int s[256];
    int tid = threadIdx.x;
    int i = blockIdx.x * 256 + tid;
    int v = (i < NN) ? g_deg[i] : 0;
    s[tid] = v;
    __syncthreads();
    for (int off = 1; off < 256; off <<= 1) {
        int t = (tid >= off) ? s[tid - off] : 0;
        __syncthreads();
        s[tid] += t;
        __syncthreads();
    }
    if (i < NN) g_scan[i] = s[tid] - v;   // exclusive
    if (tid == 255) g_bsums[blockIdx.x] = s[255];
}

__global__ void k_scan2(int nb) {  // 1 block, 512 threads
    __shared__ int s[512];
    int tid = threadIdx.x;
    int v = (tid < nb) ? g_bsums[tid] : 0;
    s[tid] = v;
    __syncthreads();
    for (int off = 1; off < 512; off <<= 1) {
        int t = (tid >= off) ? s[tid - off] : 0;
        __syncthreads();
        s[tid] += t;
        __syncthreads();
    }
    if (tid < nb) g_bsums[tid] = s[tid] - v;  // exclusive block offsets
}

__global__ void k_scan3() {
    int i = blockIdx.x * 256 + threadIdx.x;
    if (i < NN) {
        int p = g_scan[i] + g_bsums[blockIdx.x];
        g_ptr[i] = p;
        g_cursor[i] = p;
    }
    if (i == 0) g_ptr[NN] = EE;
}

__global__ void k_fill(const int* __restrict__ ei) {
    int e = blockIdx.x * blockDim.x + threadIdx.x;
    if (e < EE) {
        int d = ei[EE + e];
        int pos = atomicAdd(&g_cursor[d], 1);
        g_csr[pos] = ei[e];
    }
}

// ---------------- aggregation + (1+eps)*x + agg ----------------
// One warp per node. VEC floats per lane (F = 32*VEC).
template <int VEC>
__global__ void k_agg(const float* __restrict__ x,
                      const float* __restrict__ eps,
                      float* __restrict__ h) {
    constexpr int F = 32 * VEC;
    int w = (blockIdx.x * blockDim.x + threadIdx.x) >> 5;
    int lane = threadIdx.x & 31;
    if (w >= NN) return;
    int beg = g_ptr[w], end = g_ptr[w + 1];

    float acc[VEC];
#pragma unroll
    for (int v = 0; v < VEC; v++) acc[v] = 0.f;

    for (int e = beg; e < end; e++) {
        int j = g_csr[e];
        const float* p = x + (size_t)j * F + lane * VEC;
        if (VEC == 4) {
            float4 v4 = *reinterpret_cast<const float4*>(p);
            acc[0] += v4.x; acc[1] += v4.y; acc[2] += v4.z; acc[3] += v4.w;
        } else {
            float2 v2 = *reinterpret_cast<const float2*>(p);
            acc[0] += v2.x; acc[1] += v2.y;
        }
    }

    float ep = 1.f + eps[0];
    const float* xi = x + (size_t)w * F + lane * VEC;
    float* ho = h + (size_t)w * F + lane * VEC;
    if (VEC == 4) {
        float4 xv = *reinterpret_cast<const float4*>(xi);
        float4 o;
        o.x = ep * xv.x + acc[0];
        o.y = ep * xv.y + acc[1];
        o.z = ep * xv.z + acc[2];
        o.w = ep * xv.w + acc[3];
        *reinterpret_cast<float4*>(ho) = o;
    } else {
        float2 xv = *reinterpret_cast<const float2*>(xi);
        float2 o;
        o.x = ep * xv.x + acc[0];
        o.y = ep * xv.y + acc[1];
        *reinterpret_cast<float2*>(ho) = o;
    }
}

// ---------------- tiled fp32 GEMM:  C[n,M] = act(A[n,K] @ W[K,M] + b) ----------------
template <int K, int M>
__global__ void k_gemm(const float* __restrict__ A,
                       const float* __restrict__ W,
                       const float* __restrict__ b,
                       float* __restrict__ C,
                       int nrows, int do_relu) {
    constexpr int BM = 64, KC = 16;
    constexpr int COLG = M / 4;          // thread-columns (groups of 4)
    constexpr int ROWG = 256 / COLG;     // thread-rows
    constexpr int RPT = BM / ROWG;       // rows per thread (8 for M=128, 4 for M=64)

    __shared__ float As[KC][BM];
    __shared__ float Ws[KC][M];

    int tid = threadIdx.x;
    int row0 = (tid / COLG) * RPT;
    int col0 = (tid % COLG) * 4;
    int rbase = blockIdx.x * BM;

    float acc[RPT][4];
#pragma unroll
    for (int r = 0; r < RPT; r++)
#pragma unroll
        for (int c = 0; c < 4; c++) acc[r][c] = 0.f;

    for (int kc = 0; kc < K; kc += KC) {
        // load A tile (BM x KC), transposed into As[k][row]
#pragma unroll
        for (int i = 0; i < (BM * KC) / 256; i++) {
            int idx = tid + i * 256;
            int r = idx / KC, k = idx % KC;
            int gr = rbase + r;
            As[k][r] = (gr < nrows) ? A[(size_t)gr * K + kc + k] : 0.f;
        }
        // load W tile (KC x M)
#pragma unroll
        for (int i = 0; i < (KC * M) / 256; i++) {
            int idx = tid + i * 256;
            int k = idx / M, m = idx % M;
            Ws[k][m] = W[(size_t)(kc + k) * M + m];
        }
        __syncthreads();

#pragma unroll
        for (int k = 0; k < KC; k++) {
            float4 w4 = *reinterpret_cast<const float4*>(&Ws[k][col0]);
            float wv[4] = {w4.x, w4.y, w4.z, w4.w};
#pragma unroll
            for (int rr = 0; rr < RPT; rr += 4) {
                float4 a4 = *reinterpret_cast<const float4*>(&As[k][row0 + rr]);
                float av[4] = {a4.x, a4.y, a4.z, a4.w};
#pragma unroll
                for (int r = 0; r < 4; r++)
#pragma unroll
                    for (int c = 0; c < 4; c++)
                        acc[rr + r][c] += av[r] * wv[c];
            }
        }
        __syncthreads();
    }

    float bv[4] = {b[col0], b[col0 + 1], b[col0 + 2], b[col0 + 3]};
#pragma unroll
    for (int rr = 0; rr < RPT; rr++) {
        int gr = rbase + row0 + rr;
        if (gr < nrows) {
            float4 o;
            o.x = acc[rr][0] + bv[0];
            o.y = acc[rr][1] + bv[1];
            o.z = acc[rr][2] + bv[2];
            o.w = acc[rr][3] + bv[3];
            if (do_relu) {
                o.x = fmaxf(o.x, 0.f); o.y = fmaxf(o.y, 0.f);
                o.z = fmaxf(o.z, 0.f); o.w = fmaxf(o.w, 0.f);
            }
            *reinterpret_cast<float4*>(&C[(size_t)gr * M + col0]) = o;
        }
    }
}

// ---------------- final FC:  out[n,8] = emb[n,64] @ Wfc[64,8] + bfc ----------------
__global__ void k_fc(const float* __restrict__ emb,
                     const float* __restrict__ Wfc,
                     const float* __restrict__ bfc,
                     float* __restrict__ out, int nrows) {
    __shared__ float xs[16][64];
    __shared__ float ws[64 * 8];
    __shared__ float bs[8];
    int tid = threadIdx.x;   // 128 threads
    int base = blockIdx.x * 16;
#pragma unroll
    for (int i = 0; i < 4; i++) ws[tid + i * 128] = Wfc[tid + i * 128];
    if (tid < 8) bs[tid] = bfc[tid];
#pragma unroll
    for (int i = 0; i < 8; i++) {
        int idx = tid + i * 128;
        int r = idx / 64, c = idx % 64;
        int gr = base + r;
        xs[r][c] = (gr < nrows) ? emb[(size_t)gr * 64 + c] : 0.f;
    }
    __syncthreads();
    int nl = tid / 8, col = tid % 8;
    int node = base + nl;
    if (node < nrows) {
        float s = bs[col];
#pragma unroll
        for (int k = 0; k < 64; k++) s += xs[nl][k] * ws[k * 8 + col];
        out[(size_t)node * 8 + col] = s;
    }
}

// ---------------- launch ----------------
extern "C" void kernel_launch(void* const* d_in, const int* in_sizes, int n_in,
                              void* d_out, int out_size) {
    const float* x    = (const float*)d_in[0];
    const int*   ei   = (const int*)d_in[1];      // int32 [2, E]
    const float* eps1 = (const float*)d_in[2];
    const float* eps2 = (const float*)d_in[3];
    const float* eps3 = (const float*)d_in[4];
    const float* W1a = (const float*)d_in[5];  const float* b1a = (const float*)d_in[6];
    const float* W1b = (const float*)d_in[7];  const float* b1b = (const float*)d_in[8];
    const float* W2a = (const float*)d_in[9];  const float* b2a = (const float*)d_in[10];
    const float* W2b = (const float*)d_in[11]; const float* b2b = (const float*)d_in[12];
    const float* W3a = (const float*)d_in[13]; const float* b3a = (const float*)d_in[14];
    const float* W3b = (const float*)d_in[15]; const float* b3b = (const float*)d_in[16];
    const float* Wfc = (const float*)d_in[17]; const float* bfc = (const float*)d_in[18];

    float* out = (float*)d_out;                  // [N, 8]
    float* emb = (float*)d_out + (size_t)NN * 8; // [N, 64]

    float* h = nullptr, *hid = nullptr, *xb = nullptr;
    cudaGetSymbolAddress((void**)&h,   g_h);
    cudaGetSymbolAddress((void**)&hid, g_hid);
    cudaGetSymbolAddress((void**)&xb,  g_x);

    const int TB = 256;
    int gN  = (NN + TB - 1) / TB;      // 391
    int gE  = (EE + TB - 1) / TB;      // 6250
    int gW  = (NN * 32 + TB - 1) / TB; // one warp per node
    int gG  = (NN + 63) / 64;          // gemm blocks
    int gFC = (NN + 15) / 16;

    // ---- build CSR ----
    k_zero_deg<<<gN, TB>>>();
    k_count<<<gE, TB>>>(ei);
    k_scan1<<<gN, TB>>>();
    k_scan2<<<1, 512>>>(gN);
    k_scan3<<<gN, TB>>>();
    k_fill<<<gE, TB>>>(ei);

    // ---- layer 1: F_IN=64 -> 128 -> 128 ----
    k_agg<2><<<gW, TB>>>(x, eps1, h);
    k_gemm<64, 128><<<gG, TB>>>(h, W1a, b1a, hid, NN, 1);
    k_gemm<128, 128><<<gG, TB>>>(hid, W1b, b1b, xb, NN, 1);

    // ---- layer 2: 128 -> 128 -> 128 ----
    k_agg<4><<<gW, TB>>>(xb, eps2, h);
    k_gemm<128, 128><<<gG, TB>>>(h, W2a, b2a, hid, NN, 1);
    k_gemm<128, 128><<<gG, TB>>>(hid, W2b, b2b, xb, NN, 1);

    // ---- layer 3: 128 -> 64 -> 64 (output straight into emb region) ----
    k_agg<4><<<gW, TB>>>(xb, eps3, h);
    k_gemm<128, 64><<<gG, TB>>>(h, W3a, b3a, hid, NN, 1);
    k_gemm<64, 64><<<gG, TB>>>(hid, W3b, b3b, emb, NN, 1);

    // ---- final FC ----
    k_fc<<<gFC, 128>>>(emb, Wfc, bfc, out, NN);
}